// round 3
// baseline (speedup 1.0000x reference)
#include <cuda_runtime.h>

#define BATCH      1024
#define INPUT_DIM  1024
#define NB_K       32
#define KDIM       16
#define OUT_COLS   (INPUT_DIM + NB_K)   // 1056

// Scratch for activations, laid out [k][b][m] so each k-slice is contiguous.
__device__ float g_act[(size_t)NB_K * BATCH * KDIM];   // 2 MB

// ---- packed f32x2 helpers (sm_100+ only; 2 MACs per fma-pipe slot) --------
#define FMA_F32X2(d, a, b, c) \
    asm("fma.rn.f32x2 %0, %1, %2, %3;" : "=l"(d) : "l"(a), "l"(b), "l"(c))
#define ADD_F32X2(d, a, b) \
    asm("add.rn.f32x2 %0, %1, %2;" : "=l"(d) : "l"(a), "l"(b))
#define ABS2_F32X2(d, a) \
    asm("and.b64 %0, %1, 0x7FFFFFFF7FFFFFFF;" : "=l"(d) : "l"(a))
#define PACK_F32X2(d, lo, hi) \
    asm("mov.b64 %0, {%1, %2};" : "=l"(d) : "f"(lo), "f"(hi))
#define UNPACK_F32X2(lo, hi, v) \
    asm("mov.b64 {%0, %1}, %2;" : "=f"(lo), "=f"(hi) : "l"(v))

// ---------------------------------------------------------------------------
// Kernel A: act[k][b][m] = sum_d x[b][d] * W[k][d][m]     (f32x2 packed)
// grid = (32 k, 8 b-tiles of 128), block = 256:
//   thread t -> b = b0 + (t & 127), half h = t >> 7 handles m in [8h, 8h+8)
// ---------------------------------------------------------------------------
__global__ void __launch_bounds__(256) mbd_gemm_kernel(
    const float* __restrict__ x, const float* __restrict__ W)
{
    const int k    = blockIdx.x;
    const int b0   = blockIdx.y * 128;
    const int tid  = threadIdx.x;
    const int bl   = tid & 127;      // local b
    const int h    = tid >> 7;       // m-half

    __shared__ float sx[128][33];    // padded for conflict-free column reads
    __shared__ float sw[32][16];

    unsigned long long acc0 = 0ull, acc1 = 0ull, acc2 = 0ull, acc3 = 0ull;

    const float4* x4 = reinterpret_cast<const float4*>(x);

    for (int d0 = 0; d0 < INPUT_DIM; d0 += 32) {
        // x tile: 128 rows x 32 cols = 1024 float4, 4 per thread
#pragma unroll
        for (int i = 0; i < 4; i++) {
            int idx = tid + i * 256;
            int r = idx >> 3;
            int c = idx & 7;
            float4 v = x4[(size_t)(b0 + r) * (INPUT_DIM / 4) + (d0 >> 2) + c];
            sx[r][c * 4 + 0] = v.x;
            sx[r][c * 4 + 1] = v.y;
            sx[r][c * 4 + 2] = v.z;
            sx[r][c * 4 + 3] = v.w;
        }
        // W tile: 32 d x 16 m = 512 contiguous floats = 128 float4
        if (tid < 128) {
            const float4* w4 = reinterpret_cast<const float4*>(
                W + (size_t)k * INPUT_DIM * KDIM + (size_t)d0 * KDIM);
            reinterpret_cast<float4*>(&sw[0][0])[tid] = w4[tid];
        }
        __syncthreads();

#pragma unroll
        for (int dd = 0; dd < 32; dd++) {
            float xv = sx[bl][dd];
            unsigned long long xx;
            PACK_F32X2(xx, xv, xv);
            // 8 m values for this half: 2 x LDS.128, uniform per warp (bcast)
            const ulonglong2* wp = reinterpret_cast<const ulonglong2*>(&sw[dd][h * 8]);
            ulonglong2 wlo = wp[0];
            ulonglong2 whi = wp[1];
            FMA_F32X2(acc0, wlo.x, xx, acc0);
            FMA_F32X2(acc1, wlo.y, xx, acc1);
            FMA_F32X2(acc2, whi.x, xx, acc2);
            FMA_F32X2(acc3, whi.y, xx, acc3);
        }
        __syncthreads();
    }

    float r0, r1, r2, r3, r4, r5, r6, r7;
    UNPACK_F32X2(r0, r1, acc0);
    UNPACK_F32X2(r2, r3, acc1);
    UNPACK_F32X2(r4, r5, acc2);
    UNPACK_F32X2(r6, r7, acc3);
    float4* o4 = reinterpret_cast<float4*>(
        g_act + ((size_t)k * BATCH + b0 + bl) * KDIM + h * 8);
    o4[0] = make_float4(r0, r1, r2, r3);
    o4[1] = make_float4(r4, r5, r6, r7);
}

// ---------------------------------------------------------------------------
// Kernel B: feat[b][k] = sum_c exp(-sum_m |act[k][b][m] - act[k][c][m]|)
// grid = (32 k, 8 b-tiles of 128), block 256:
//   thread t -> b = b0 + (t & 127), half h = t >> 7 sums c in [512h, 512h+512)
// Whole negated act_k slice staged in 64KB dynamic smem once.
// ---------------------------------------------------------------------------
extern __shared__ float4 sneg[];   // 1024 rows x 4 float4 = 64 KB

__global__ void __launch_bounds__(256) mbd_pairwise_kernel(float* __restrict__ out)
{
    const int k   = blockIdx.x;
    const int tid = threadIdx.x;
    const int bl  = tid & 127;
    const int h   = tid >> 7;
    const int b   = blockIdx.y * 128 + bl;

    __shared__ float sred[256];

    const float4* actk = reinterpret_cast<const float4*>(
        g_act + (size_t)k * BATCH * KDIM);

    // stage NEGATED slice: 4096 float4 / 256 threads = 16 each
#pragma unroll
    for (int i = 0; i < 16; i++) {
        int idx = tid + i * 256;
        float4 v = actk[idx];
        v.x = -v.x; v.y = -v.y; v.z = -v.z; v.w = -v.w;
        sneg[idx] = v;
    }

    // my own activation row (positive), packed as 8 f32x2
    unsigned long long a[8];
    {
        float4 a0 = actk[b * 4 + 0];
        float4 a1 = actk[b * 4 + 1];
        float4 a2 = actk[b * 4 + 2];
        float4 a3 = actk[b * 4 + 3];
        PACK_F32X2(a[0], a0.x, a0.y);  PACK_F32X2(a[1], a0.z, a0.w);
        PACK_F32X2(a[2], a1.x, a1.y);  PACK_F32X2(a[3], a1.z, a1.w);
        PACK_F32X2(a[4], a2.x, a2.y);  PACK_F32X2(a[5], a2.z, a2.w);
        PACK_F32X2(a[6], a3.x, a3.y);  PACK_F32X2(a[7], a3.z, a3.w);
    }
    __syncthreads();

    float f = 0.f;
    const int c_end = h * 512 + 512;

#pragma unroll 4
    for (int c = h * 512; c < c_end; c++) {
        const ulonglong2* vp = reinterpret_cast<const ulonglong2*>(&sneg[c * 4]);
        ulonglong2 v0 = vp[0], v1 = vp[1], v2 = vp[2], v3 = vp[3];

        unsigned long long d0, d1, d2, d3, d4, d5, d6, d7;
        ADD_F32X2(d0, a[0], v0.x);  ADD_F32X2(d1, a[1], v0.y);
        ADD_F32X2(d2, a[2], v1.x);  ADD_F32X2(d3, a[3], v1.y);
        ADD_F32X2(d4, a[4], v2.x);  ADD_F32X2(d5, a[5], v2.y);
        ADD_F32X2(d6, a[6], v3.x);  ADD_F32X2(d7, a[7], v3.y);

        ABS2_F32X2(d0, d0);  ABS2_F32X2(d1, d1);
        ABS2_F32X2(d2, d2);  ABS2_F32X2(d3, d3);
        ABS2_F32X2(d4, d4);  ABS2_F32X2(d5, d5);
        ABS2_F32X2(d6, d6);  ABS2_F32X2(d7, d7);

        ADD_F32X2(d0, d0, d1);
        ADD_F32X2(d2, d2, d3);
        ADD_F32X2(d4, d4, d5);
        ADD_F32X2(d6, d6, d7);
        ADD_F32X2(d0, d0, d2);
        ADD_F32X2(d4, d4, d6);
        ADD_F32X2(d0, d0, d4);

        float slo, shi;
        UNPACK_F32X2(slo, shi, d0);
        f += __expf(-(slo + shi));
    }

    // combine the two c-halves of each b
    sred[tid] = f;
    __syncthreads();
    if (h == 0)
        out[(size_t)b * OUT_COLS + INPUT_DIM + k] = f + sred[tid + 128];
}

// ---------------------------------------------------------------------------
// Kernel C: copy x into out[:, 0:1024] (float4)
// ---------------------------------------------------------------------------
__global__ void __launch_bounds__(256) mbd_copy_kernel(
    const float* __restrict__ x, float* __restrict__ out)
{
    const float4* x4 = reinterpret_cast<const float4*>(x);
    float4*       o4 = reinterpret_cast<float4*>(out);
    int idx0 = blockIdx.x * 256 + threadIdx.x;
    const int stride = gridDim.x * 256;
    const int n4 = BATCH * (INPUT_DIM / 4);          // 262144
#pragma unroll 4
    for (int idx = idx0; idx < n4; idx += stride) {
        int bRow = idx >> 8;
        int j    = idx & 255;
        o4[(size_t)bRow * (OUT_COLS / 4) + j] = x4[idx];
    }
}

extern "C" void kernel_launch(void* const* d_in, const int* in_sizes, int n_in,
                              void* d_out, int out_size)
{
    (void)in_sizes; (void)n_in; (void)out_size;
    const float* x = (const float*)d_in[0];
    const float* W = (const float*)d_in[1];
    float* out = (float*)d_out;

    static const int smem_bytes = BATCH * KDIM * (int)sizeof(float);  // 64 KB
    cudaFuncSetAttribute(mbd_pairwise_kernel,
                         cudaFuncAttributeMaxDynamicSharedMemorySize, smem_bytes);

    mbd_gemm_kernel<<<dim3(NB_K, BATCH / 128), 256>>>(x, W);
    mbd_pairwise_kernel<<<dim3(NB_K, BATCH / 128), 256, smem_bytes>>>(out);
    mbd_copy_kernel<<<256, 256>>>(x, out);
}

// round 4
// speedup vs baseline: 1.2041x; 1.2041x over previous
#include <cuda_runtime.h>

#define BATCH      1024
#define INPUT_DIM  1024
#define NB_K       32
#define KDIM       16
#define OUT_COLS   (INPUT_DIM + NB_K)   // 1056
#define DSPLIT     4
#define DCHUNK     (INPUT_DIM / DSPLIT) // 256

// Partial activations per d-split, then reduced into g_act.
__device__ float g_part[(size_t)DSPLIT * NB_K * BATCH * KDIM];  // 8 MB
__device__ float g_act [(size_t)NB_K * BATCH * KDIM];           // 2 MB

// ---- packed f32x2 helpers ------------------------------------------------
#define FMA_F32X2(d, a, b, c) \
    asm("fma.rn.f32x2 %0, %1, %2, %3;" : "=l"(d) : "l"(a), "l"(b), "l"(c))
#define PACK_F32X2(d, lo, hi) \
    asm("mov.b64 %0, {%1, %2};" : "=l"(d) : "f"(lo), "f"(hi))
#define UNPACK_F32X2(lo, hi, v) \
    asm("mov.b64 {%0, %1}, %2;" : "=f"(lo), "=f"(hi) : "l"(v))

// ---------------------------------------------------------------------------
// Kernel A: partial GEMM over one d-chunk of 256.
// grid = (32 k, 4 b-tiles of 256, 4 d-splits), block = 256.
// Thread t: bl = t&127 -> b rows {b0+bl, b0+bl+128}; h = t>>7 -> m in [8h,8h+8).
// Inner loop: 2 LDS.32 (x) + 2 LDS.128 (w, broadcast) + 8 FMA2.
// ---------------------------------------------------------------------------
__global__ void __launch_bounds__(256) mbd_gemm_kernel(
    const float* __restrict__ x, const float* __restrict__ W)
{
    const int k     = blockIdx.x;
    const int b0    = blockIdx.y * 256;
    const int dbase = blockIdx.z * DCHUNK;
    const int tid   = threadIdx.x;
    const int bl    = tid & 127;
    const int h     = tid >> 7;

    __shared__ float sx[256][33];    // 256 b-rows x 32 d, padded
    __shared__ float sw[32][16];

    unsigned long long accA0 = 0ull, accA1 = 0ull, accA2 = 0ull, accA3 = 0ull;
    unsigned long long accB0 = 0ull, accB1 = 0ull, accB2 = 0ull, accB3 = 0ull;

    const float4* x4 = reinterpret_cast<const float4*>(x);

    for (int d0 = dbase; d0 < dbase + DCHUNK; d0 += 32) {
        // x tile: 256 rows x 32 d = 2048 float4, 8 per thread
#pragma unroll
        for (int i = 0; i < 8; i++) {
            int idx = tid + i * 256;
            int r = idx >> 3;
            int c = idx & 7;
            float4 v = x4[(size_t)(b0 + r) * (INPUT_DIM / 4) + (d0 >> 2) + c];
            sx[r][c * 4 + 0] = v.x;
            sx[r][c * 4 + 1] = v.y;
            sx[r][c * 4 + 2] = v.z;
            sx[r][c * 4 + 3] = v.w;
        }
        // W tile: 32 d x 16 m = 512 contiguous floats = 128 float4
        if (tid < 128) {
            const float4* w4 = reinterpret_cast<const float4*>(
                W + (size_t)k * INPUT_DIM * KDIM + (size_t)d0 * KDIM);
            reinterpret_cast<float4*>(&sw[0][0])[tid] = w4[tid];
        }
        __syncthreads();

#pragma unroll
        for (int dd = 0; dd < 32; dd++) {
            float xa = sx[bl][dd];
            float xb = sx[bl + 128][dd];
            unsigned long long xxa, xxb;
            PACK_F32X2(xxa, xa, xa);
            PACK_F32X2(xxb, xb, xb);
            const ulonglong2* wp = reinterpret_cast<const ulonglong2*>(&sw[dd][h * 8]);
            ulonglong2 wlo = wp[0];
            ulonglong2 whi = wp[1];
            FMA_F32X2(accA0, wlo.x, xxa, accA0);
            FMA_F32X2(accA1, wlo.y, xxa, accA1);
            FMA_F32X2(accA2, whi.x, xxa, accA2);
            FMA_F32X2(accA3, whi.y, xxa, accA3);
            FMA_F32X2(accB0, wlo.x, xxb, accB0);
            FMA_F32X2(accB1, wlo.y, xxb, accB1);
            FMA_F32X2(accB2, whi.x, xxb, accB2);
            FMA_F32X2(accB3, whi.y, xxb, accB3);
        }
        __syncthreads();
    }

    float* base = g_part + ((size_t)blockIdx.z * NB_K + k) * BATCH * KDIM;
    {
        float r0, r1, r2, r3, r4, r5, r6, r7;
        UNPACK_F32X2(r0, r1, accA0); UNPACK_F32X2(r2, r3, accA1);
        UNPACK_F32X2(r4, r5, accA2); UNPACK_F32X2(r6, r7, accA3);
        float4* o4 = reinterpret_cast<float4*>(
            base + (size_t)(b0 + bl) * KDIM + h * 8);
        o4[0] = make_float4(r0, r1, r2, r3);
        o4[1] = make_float4(r4, r5, r6, r7);
    }
    {
        float r0, r1, r2, r3, r4, r5, r6, r7;
        UNPACK_F32X2(r0, r1, accB0); UNPACK_F32X2(r2, r3, accB1);
        UNPACK_F32X2(r4, r5, accB2); UNPACK_F32X2(r6, r7, accB3);
        float4* o4 = reinterpret_cast<float4*>(
            base + (size_t)(b0 + bl + 128) * KDIM + h * 8);
        o4[0] = make_float4(r0, r1, r2, r3);
        o4[1] = make_float4(r4, r5, r6, r7);
    }
}

// ---------------------------------------------------------------------------
// Kernel A2: g_act = sum over the 4 d-split partials (float4 granularity).
// ---------------------------------------------------------------------------
__global__ void __launch_bounds__(256) mbd_reduce_kernel()
{
    const size_t n4 = (size_t)NB_K * BATCH * KDIM / 4;   // 131072
    size_t i = (size_t)blockIdx.x * 256 + threadIdx.x;
    if (i >= n4) return;
    const float4* p = reinterpret_cast<const float4*>(g_part);
    float4 a = p[i];
    float4 b = p[i + n4];
    float4 c = p[i + 2 * n4];
    float4 d = p[i + 3 * n4];
    float4 r;
    r.x = (a.x + b.x) + (c.x + d.x);
    r.y = (a.y + b.y) + (c.y + d.y);
    r.z = (a.z + b.z) + (c.z + d.z);
    r.w = (a.w + b.w) + (c.w + d.w);
    reinterpret_cast<float4*>(g_act)[i] = r;
}

// ---------------------------------------------------------------------------
// Kernel B: feat[b][k] = sum_c exp(-sum_m |act[k][b][m] - act[k][c][m]|)
// (R1-proven version, unchanged)
// grid = (32 k, 4 b-tiles), block = 256 (one b per thread).
// ---------------------------------------------------------------------------
__global__ void __launch_bounds__(256) mbd_pairwise_kernel(float* __restrict__ out)
{
    const int k   = blockIdx.x;
    const int tid = threadIdx.x;
    const int b   = blockIdx.y * 256 + tid;

    __shared__ float4 sa[512 * 4];   // 512 rows x 16 floats = 32 KB

    const float4* actk = reinterpret_cast<const float4*>(
        g_act + (size_t)k * BATCH * KDIM);

    float4 a0 = actk[b * 4 + 0];
    float4 a1 = actk[b * 4 + 1];
    float4 a2 = actk[b * 4 + 2];
    float4 a3 = actk[b * 4 + 3];

    float f = 0.f;

    for (int c0 = 0; c0 < BATCH; c0 += 512) {
        __syncthreads();
#pragma unroll
        for (int i = 0; i < 8; i++)
            sa[tid + i * 256] = actk[c0 * 4 + tid + i * 256];
        __syncthreads();

#pragma unroll 4
        for (int c = 0; c < 512; c++) {
            float4 v0 = sa[c * 4 + 0];
            float4 v1 = sa[c * 4 + 1];
            float4 v2 = sa[c * 4 + 2];
            float4 v3 = sa[c * 4 + 3];
            float s0 = fabsf(a0.x - v0.x) + fabsf(a0.y - v0.y)
                     + fabsf(a0.z - v0.z) + fabsf(a0.w - v0.w);
            float s1 = fabsf(a1.x - v1.x) + fabsf(a1.y - v1.y)
                     + fabsf(a1.z - v1.z) + fabsf(a1.w - v1.w);
            float s2 = fabsf(a2.x - v2.x) + fabsf(a2.y - v2.y)
                     + fabsf(a2.z - v2.z) + fabsf(a2.w - v2.w);
            float s3 = fabsf(a3.x - v3.x) + fabsf(a3.y - v3.y)
                     + fabsf(a3.z - v3.z) + fabsf(a3.w - v3.w);
            float s = (s0 + s1) + (s2 + s3);
            f += __expf(-s);
        }
    }

    out[(size_t)b * OUT_COLS + INPUT_DIM + k] = f;
}

// ---------------------------------------------------------------------------
// Kernel C: copy x into out[:, 0:1024] (float4)
// ---------------------------------------------------------------------------
__global__ void __launch_bounds__(256) mbd_copy_kernel(
    const float* __restrict__ x, float* __restrict__ out)
{
    const float4* x4 = reinterpret_cast<const float4*>(x);
    float4*       o4 = reinterpret_cast<float4*>(out);
    int idx0 = blockIdx.x * 256 + threadIdx.x;
    const int stride = gridDim.x * 256;
    const int n4 = BATCH * (INPUT_DIM / 4);          // 262144
#pragma unroll 4
    for (int idx = idx0; idx < n4; idx += stride) {
        int bRow = idx >> 8;
        int j    = idx & 255;
        o4[(size_t)bRow * (OUT_COLS / 4) + j] = x4[idx];
    }
}

extern "C" void kernel_launch(void* const* d_in, const int* in_sizes, int n_in,
                              void* d_out, int out_size)
{
    (void)in_sizes; (void)n_in; (void)out_size;
    const float* x = (const float*)d_in[0];
    const float* W = (const float*)d_in[1];
    float* out = (float*)d_out;

    mbd_gemm_kernel<<<dim3(NB_K, BATCH / 256, DSPLIT), 256>>>(x, W);
    mbd_reduce_kernel<<<(NB_K * BATCH * KDIM / 4 + 255) / 256, 256>>>();
    mbd_pairwise_kernel<<<dim3(NB_K, BATCH / 256), 256>>>(out);
    mbd_copy_kernel<<<256, 256>>>(x, out);
}